// round 7
// baseline (speedup 1.0000x reference)
#include <cuda_runtime.h>
#include <math.h>

#define HID 32
#define MAXN 10240
#define MAXSEF 1100000

// device scratch (no allocs allowed)
__device__ float g_A[2][MAXN * HID];  // z @ M_w[0:32], double-buffered
__device__ float g_Bc[MAXN * HID];    // z @ M_w[32:64] + M_b
__device__ float g_z[MAXN * HID];     // current z
__device__ int2  g_pair[MAXSEF];      // (src, edge_feat bits) re-laid [n][k]
__device__ float g_blockmax[8 * 2048];

// ---------------------------------------------------------------------------
// Prologue: re-lay (src, edge_feat) into per-node contiguous int2 pairs.
// dst[e] == e % N.
// ---------------------------------------------------------------------------
__global__ void k_prep(const float* __restrict__ edges,
                       const int* __restrict__ src,
                       int N, int E, int Kc, int KS, int Erem) {
    int o = blockIdx.x * blockDim.x + threadIdx.x;
    if (o >= N * KS) return;
    int n = o / KS, k = o - n * KS;
    int kn = Kc + (n < Erem ? 1 : 0);
    if (k >= kn) return;
    int e = k * N + n;
    int s = __ldg(src + e);
    float f = __ldg(edges + (long)s * N + n);
    g_pair[o] = make_int2(s, __float_as_int(f));
}

// ---------------------------------------------------------------------------
// Init kernel: z0 = enc([states0, 0, pri]); A0 -> parity 0; Bc0; preds[0].
// Warp handles 2 nodes, lane = dim j. Grid: ceil(N/16).
// ---------------------------------------------------------------------------
__global__ void __launch_bounds__(256) k_init(
        const float* __restrict__ states0, const float* __restrict__ pri,
        const float* __restrict__ encw, const float* __restrict__ encb,
        const float* __restrict__ Mw,   const float* __restrict__ Mb,
        float* __restrict__ out, int N) {
    __shared__ float s_Mw[64 * HID];
    __shared__ __align__(8) float s_zs[HID][18];
    int tid = threadIdx.x;
    for (int i = tid; i < 64 * HID; i += 256) s_Mw[i] = Mw[i];
    __syncthreads();

    int w = tid >> 5, j = tid & 31, qb = w * 2;
    int n0 = blockIdx.x * 16 + qb;
    if (n0 >= N) return;
    const float2 st2 = *(const float2*)(states0 + n0);
    const float2 p2  = *(const float2*)(pri + n0);
    float eb = __ldg(encb + j);
    float w0 = __ldg(encw + j), w33 = __ldg(encw + 33 * HID + j);
    float z0 = fmaf(st2.x, w0, fmaf(p2.x, w33, eb));
    float z1 = fmaf(st2.y, w0, fmaf(p2.y, w33, eb));
    if (j < 2) out[n0 + j] = (j == 0) ? st2.x : st2.y;

    s_zs[j][qb + 0] = z0; s_zs[j][qb + 1] = z1;
    __syncwarp();
    float A0 = 0, A1 = 0, B0 = 0, B1 = 0;
    #pragma unroll
    for (int i = 0; i < HID; i++) {
        float wa = s_Mw[i * HID + j], wb = s_Mw[(HID + i) * HID + j];
        float2 zq = *(const float2*)&s_zs[i][qb];
        A0 = fmaf(zq.x, wa, A0); B0 = fmaf(zq.x, wb, B0);
        A1 = fmaf(zq.y, wa, A1); B1 = fmaf(zq.y, wb, B1);
    }
    float mb = __ldg(Mb + j);
    int r = n0 * HID + j;
    g_z[r] = z0; g_z[r + HID] = z1;
    g_A[0][r] = A0; g_A[0][r + HID] = A1;
    g_Bc[r] = B0 + mb; g_Bc[r + HID] = B1 + mb;
}

// ---------------------------------------------------------------------------
// Fused step kernel: 8 warps, ONE node per warp -> 8 nodes/block, grid 1250.
// Edge max (A from parity `par`, software-pipelined gathers) + node update.
// ---------------------------------------------------------------------------
__global__ void __launch_bounds__(256) k_step(int step, int par,
        const float* __restrict__ pri,
        const float* __restrict__ encw, const float* __restrict__ encb,
        const float* __restrict__ Mw,   const float* __restrict__ Mb,
        const float* __restrict__ Uw,   const float* __restrict__ Ub,
        const float* __restrict__ dnw,  const float* __restrict__ dnb,
        const float* __restrict__ duw,  const float* __restrict__ dub,
        const float* __restrict__ termw,const float* __restrict__ termb,
        float* __restrict__ out, int N, int T, int Kc, int KS, int Erem) {
    __shared__ float  s_encw[34 * HID];
    __shared__ __align__(8) float2 s_Uw2[HID][HID];  // (Uw[i][j], Uw[32+i][j])
    __shared__ __align__(8) float2 s_Mw2[HID][HID];  // (Mw[i][j], Mw[32+i][j])
    __shared__ float  s_dnw[64];
    __shared__ float  s_duw[65];
    __shared__ float  s_termw[HID];
    __shared__ __align__(8) int2   s_p[8][104];
    __shared__ __align__(8) float2 s_zu[8][HID];
    __shared__ float  s_red[8];

    int tid = threadIdx.x;
    bool lastStep = (step >= T - 2);

    // weight prefetch into smem (packed float2) — hidden behind edge phase
    if (!lastStep) {
        for (int i = tid; i < 34 * HID; i += 256) s_encw[i] = encw[i];
        for (int idx = tid; idx < HID * HID; idx += 256) {
            int i = idx >> 5, j2 = idx & 31;
            s_Mw2[i][j2] = make_float2(Mw[i * HID + j2], Mw[(HID + i) * HID + j2]);
        }
    }
    for (int idx = tid; idx < HID * HID; idx += 256) {
        int i = idx >> 5, j2 = idx & 31;
        s_Uw2[i][j2] = make_float2(Uw[i * HID + j2], Uw[(HID + i) * HID + j2]);
    }
    if (tid < 64) s_dnw[tid] = dnw[tid];
    if (tid < 65) s_duw[tid] = duw[tid];
    if (tid < HID) s_termw[tid] = termw[tid];

    int w = tid >> 5, j = tid & 31;
    int n = blockIdx.x * 8 + w;
    bool active = (n < N);
    float locmax = -INFINITY;

    // ---------------- edge phase: pipelined gathers, MLP 16 ----------------
    float u = 0.f, z = 0.f;
    if (active) {
        int r = n * HID + j;
        z = g_z[r];                           // prefetch, overlaps gathers
        float bc = g_Bc[r];
        const float* __restrict__ Aold = g_A[par];
        float fw = __ldg(Mw + 64 * HID + j);
        int kn = Kc + (n < Erem ? 1 : 0);
        const int base = n * KS;
        for (int kk = j; kk < kn; kk += 32)
            s_p[w][kk] = g_pair[base + kk];
        __syncwarp();
        float m0 = -INFINITY, m1 = -INFINITY, m2 = -INFINITY, m3 = -INFINITY;
        int k = 0;
        if (kn >= 8) {
            float a0 = Aold[s_p[w][0].x * HID + j];
            float a1 = Aold[s_p[w][1].x * HID + j];
            float a2 = Aold[s_p[w][2].x * HID + j];
            float a3 = Aold[s_p[w][3].x * HID + j];
            float a4 = Aold[s_p[w][4].x * HID + j];
            float a5 = Aold[s_p[w][5].x * HID + j];
            float a6 = Aold[s_p[w][6].x * HID + j];
            float a7 = Aold[s_p[w][7].x * HID + j];
            for (k = 8; k + 8 <= kn; k += 8) {
                float b0 = Aold[s_p[w][k + 0].x * HID + j];
                float b1 = Aold[s_p[w][k + 1].x * HID + j];
                float b2 = Aold[s_p[w][k + 2].x * HID + j];
                float b3 = Aold[s_p[w][k + 3].x * HID + j];
                float b4 = Aold[s_p[w][k + 4].x * HID + j];
                float b5 = Aold[s_p[w][k + 5].x * HID + j];
                float b6 = Aold[s_p[w][k + 6].x * HID + j];
                float b7 = Aold[s_p[w][k + 7].x * HID + j];
                m0 = fmaxf(m0, fmaf(__int_as_float(s_p[w][k - 8].y), fw, a0));
                m1 = fmaxf(m1, fmaf(__int_as_float(s_p[w][k - 7].y), fw, a1));
                m2 = fmaxf(m2, fmaf(__int_as_float(s_p[w][k - 6].y), fw, a2));
                m3 = fmaxf(m3, fmaf(__int_as_float(s_p[w][k - 5].y), fw, a3));
                m0 = fmaxf(m0, fmaf(__int_as_float(s_p[w][k - 4].y), fw, a4));
                m1 = fmaxf(m1, fmaf(__int_as_float(s_p[w][k - 3].y), fw, a5));
                m2 = fmaxf(m2, fmaf(__int_as_float(s_p[w][k - 2].y), fw, a6));
                m3 = fmaxf(m3, fmaf(__int_as_float(s_p[w][k - 1].y), fw, a7));
                a0 = b0; a1 = b1; a2 = b2; a3 = b3;
                a4 = b4; a5 = b5; a6 = b6; a7 = b7;
            }
            m0 = fmaxf(m0, fmaf(__int_as_float(s_p[w][k - 8].y), fw, a0));
            m1 = fmaxf(m1, fmaf(__int_as_float(s_p[w][k - 7].y), fw, a1));
            m2 = fmaxf(m2, fmaf(__int_as_float(s_p[w][k - 6].y), fw, a2));
            m3 = fmaxf(m3, fmaf(__int_as_float(s_p[w][k - 5].y), fw, a3));
            m0 = fmaxf(m0, fmaf(__int_as_float(s_p[w][k - 4].y), fw, a4));
            m1 = fmaxf(m1, fmaf(__int_as_float(s_p[w][k - 3].y), fw, a5));
            m2 = fmaxf(m2, fmaf(__int_as_float(s_p[w][k - 2].y), fw, a6));
            m3 = fmaxf(m3, fmaf(__int_as_float(s_p[w][k - 1].y), fw, a7));
        }
        for (; k < kn; k++) {
            int2 p = s_p[w][k];
            m0 = fmaxf(m0, fmaf(__int_as_float(p.y), fw, Aold[p.x * HID + j]));
        }
        u = bc + fmaxf(fmaxf(m0, m1), fmaxf(m2, m3));
    }
    __syncthreads();   // weights ready

    // ---------------- node phase: per-warp, packed smem broadcasts ----------
    if (active) {
        int r = n * HID + j;
        s_zu[w][j] = make_float2(z, u);
        __syncwarp();
        float nhA = __ldg(Ub + j), nhB = 0.f;
        #pragma unroll
        for (int i = 0; i < HID; i += 2) {
            float2 w0 = s_Uw2[i][j],     zu0 = s_zu[w][i];
            float2 w1 = s_Uw2[i + 1][j], zu1 = s_zu[w][i + 1];
            nhA = fmaf(zu0.x, w0.x, nhA); nhA = fmaf(zu0.y, w0.y, nhA);
            nhB = fmaf(zu1.x, w1.x, nhB); nhB = fmaf(zu1.y, w1.y, nhB);
        }
        float nh = nhA + nhB;
        float l  = nh * s_termw[j];
        float qd = fmaf(nh, s_dnw[j], z * s_dnw[HID + j]);
        float rd = fmaf(nh, s_duw[j], z * s_duw[HID + j]);
        #pragma unroll
        for (int o = 16; o; o >>= 1) {
            l  += __shfl_xor_sync(0xffffffffu, l, o);
            qd += __shfl_xor_sync(0xffffffffu, qd, o);
            rd += __shfl_xor_sync(0xffffffffu, rd, o);
        }
        locmax = l + __ldg(termb);
        float nn = qd + __ldg(dnb);
        float ns = fmaf(nn, s_duw[64], rd + __ldg(dub));
        if (j == 0) {
            out[(step + 1) * N + n] = ns;                  // preds
            out[T * N + T + n * (T - 1) + step] = nn;      // preds_nextnode
        }
        if (!lastStep) {
            // broadcast nh via s_zu.x
            s_zu[w][j].x = nh;
            __syncwarp();
            float pr = __ldg(pri + n);
            float znA = fmaf(ns, s_encw[j], fmaf(pr, s_encw[33 * HID + j], __ldg(encb + j)));
            float znB = 0.f;
            #pragma unroll
            for (int i = 0; i < HID; i += 2) {
                znA = fmaf(s_zu[w][i].x,     s_encw[(1 + i) * HID + j], znA);
                znB = fmaf(s_zu[w][i + 1].x, s_encw[(2 + i) * HID + j], znB);
            }
            float zn = znA + znB;
            s_zu[w][j].y = zn;
            __syncwarp();
            float A0 = 0, A1 = 0, B0 = 0, B1 = 0;
            #pragma unroll
            for (int i = 0; i < HID; i += 2) {
                float zi0 = s_zu[w][i].y, zi1 = s_zu[w][i + 1].y;
                float2 mw0 = s_Mw2[i][j], mw1 = s_Mw2[i + 1][j];
                A0 = fmaf(zi0, mw0.x, A0); B0 = fmaf(zi0, mw0.y, B0);
                A1 = fmaf(zi1, mw1.x, A1); B1 = fmaf(zi1, mw1.y, B1);
            }
            float* __restrict__ Anew = g_A[par ^ 1];
            g_z[r] = zn;
            Anew[r] = A0 + A1;
            g_Bc[r] = B0 + B1 + __ldg(Mb + j);
        }
    }

    if (j == 0) s_red[w] = active ? locmax : -INFINITY;
    __syncthreads();
    if (tid == 0) {
        float m = -INFINITY;
        #pragma unroll
        for (int ww = 0; ww < 8; ww++) m = fmaxf(m, s_red[ww]);
        g_blockmax[step * 2048 + blockIdx.x] = m;
    }
}

// ---------------------------------------------------------------------------
// Finalize: preds_stop[0]=0, preds_stop[t+1]=sigmoid(max_blocks blockmax[t])
// ---------------------------------------------------------------------------
__global__ void k_final(float* __restrict__ out, int N, int T, int nblocks) {
    __shared__ float s_red[256];
    int t = blockIdx.x;
    float m = -INFINITY;
    for (int b = threadIdx.x; b < nblocks; b += blockDim.x)
        m = fmaxf(m, g_blockmax[t * 2048 + b]);
    s_red[threadIdx.x] = m;
    __syncthreads();
    for (int s = 128; s; s >>= 1) {
        if (threadIdx.x < s)
            s_red[threadIdx.x] = fmaxf(s_red[threadIdx.x], s_red[threadIdx.x + s]);
        __syncthreads();
    }
    if (threadIdx.x == 0) {
        float v = s_red[0];
        out[T * N + 1 + t] = 1.0f / (1.0f + expf(-v));
        if (t == 0) out[T * N] = 0.0f;
    }
}

// ---------------------------------------------------------------------------
extern "C" void kernel_launch(void* const* d_in, const int* in_sizes, int n_in,
                              void* d_out, int out_size) {
    const float* states   = (const float*)d_in[0];
    const float* priority = (const float*)d_in[1];
    const float* edges    = (const float*)d_in[2];
    const int*   src      = (const int*)d_in[3];
    const float* enc_w    = (const float*)d_in[5];
    const float* enc_b    = (const float*)d_in[6];
    const float* M_w      = (const float*)d_in[7];
    const float* M_b      = (const float*)d_in[8];
    const float* U_w      = (const float*)d_in[9];
    const float* U_b      = (const float*)d_in[10];
    const float* dn_w     = (const float*)d_in[11];
    const float* dn_b     = (const float*)d_in[12];
    const float* du_w     = (const float*)d_in[13];
    const float* du_b     = (const float*)d_in[14];
    const float* term_w   = (const float*)d_in[15];
    const float* term_b   = (const float*)d_in[16];
    float* out = (float*)d_out;

    int N = in_sizes[1];
    int E = in_sizes[3];
    int T = in_sizes[0] / N;
    int Kc = E / N;
    int Erem = E - Kc * N;
    int KS = Kc + (Erem ? 1 : 0);

    int ptotal = N * KS;
    k_prep<<<(ptotal + 255) / 256, 256>>>(edges, src, N, E, Kc, KS, Erem);

    int nbi = (N + 15) / 16;
    k_init<<<nbi, 256>>>(states, priority, enc_w, enc_b, M_w, M_b, out, N);

    int nb = (N + 7) / 8;   // step kernel: 8 nodes/block
    for (int t = 0; t < T - 1; t++) {
        k_step<<<nb, 256>>>(t, t & 1, priority, enc_w, enc_b, M_w, M_b,
                            U_w, U_b, dn_w, dn_b, du_w, du_b,
                            term_w, term_b, out, N, T, Kc, KS, Erem);
    }
    k_final<<<T - 1, 256>>>(out, N, T, nb);
}

// round 8
// speedup vs baseline: 1.9556x; 1.9556x over previous
#include <cuda_runtime.h>
#include <math.h>

#define HID 32
#define MAXN 10240
#define MAXSEF 1100000

// device scratch (no allocs allowed)
__device__ __align__(16) float g_A[2][MAXN * HID];  // z @ M_w[0:32], dbl-buffered
__device__ float g_Bc[MAXN * HID];    // z @ M_w[32:64] + M_b
__device__ float g_z[MAXN * HID];     // current z
__device__ __align__(16) int2 g_pair[MAXSEF];  // (src, ef bits) [n][k], padded
__device__ float g_blockmax[8 * 1024];

// ---------------------------------------------------------------------------
// Prologue: re-lay (src, edge_feat) into per-node int2 pairs, padded to KS8
// (multiple of 8) with duplicates of edge 0 (idempotent under max).
// dst[e] == e % N.
// ---------------------------------------------------------------------------
__global__ void k_prep(const float* __restrict__ edges,
                       const int* __restrict__ src,
                       int N, int E, int Kc, int KS8, int Erem) {
    int o = blockIdx.x * blockDim.x + threadIdx.x;
    if (o >= N * KS8) return;
    int n = o / KS8, k = o - n * KS8;
    int kn = Kc + (n < Erem ? 1 : 0);
    int e = (k < kn) ? (k * N + n) : n;   // pad: duplicate edge k=0
    int s = __ldg(src + e);
    float f = __ldg(edges + (long)s * N + n);
    g_pair[o] = make_int2(s, __float_as_int(f));
}

// ---------------------------------------------------------------------------
// Init kernel: z0 = enc([states0, 0, pri]); A0 -> parity 0; Bc0; preds[0].
// Warp handles 2 nodes, lane = dim j. Grid: ceil(N/16).
// ---------------------------------------------------------------------------
__global__ void __launch_bounds__(256) k_init(
        const float* __restrict__ states0, const float* __restrict__ pri,
        const float* __restrict__ encw, const float* __restrict__ encb,
        const float* __restrict__ Mw,   const float* __restrict__ Mb,
        float* __restrict__ out, int N) {
    __shared__ float s_Mw[64 * HID];
    __shared__ __align__(8) float s_zs[HID][18];
    int tid = threadIdx.x;
    for (int i = tid; i < 64 * HID; i += 256) s_Mw[i] = Mw[i];
    __syncthreads();

    int w = tid >> 5, j = tid & 31, qb = w * 2;
    int n0 = blockIdx.x * 16 + qb;
    if (n0 >= N) return;
    const float2 st2 = *(const float2*)(states0 + n0);
    const float2 p2  = *(const float2*)(pri + n0);
    float eb = __ldg(encb + j);
    float w0 = __ldg(encw + j), w33 = __ldg(encw + 33 * HID + j);
    float z0 = fmaf(st2.x, w0, fmaf(p2.x, w33, eb));
    float z1 = fmaf(st2.y, w0, fmaf(p2.y, w33, eb));
    if (j < 2) out[n0 + j] = (j == 0) ? st2.x : st2.y;

    s_zs[j][qb + 0] = z0; s_zs[j][qb + 1] = z1;
    __syncwarp();
    float A0 = 0, A1 = 0, B0 = 0, B1 = 0;
    #pragma unroll
    for (int i = 0; i < HID; i++) {
        float wa = s_Mw[i * HID + j], wb = s_Mw[(HID + i) * HID + j];
        float2 zq = *(const float2*)&s_zs[i][qb];
        A0 = fmaf(zq.x, wa, A0); B0 = fmaf(zq.x, wb, B0);
        A1 = fmaf(zq.y, wa, A1); B1 = fmaf(zq.y, wb, B1);
    }
    float mb = __ldg(Mb + j);
    int r = n0 * HID + j;
    g_z[r] = z0; g_z[r + HID] = z1;
    g_A[0][r] = A0; g_A[0][r + HID] = A1;
    g_Bc[r] = B0 + mb; g_Bc[r + HID] = B1 + mb;
}

// ---------------------------------------------------------------------------
// Fused step kernel: 8 warps, 2 nodes/warp -> 16 nodes/block, grid 625.
// Edge phase: lane-group float4 gathers (warp eats 4 edges per LDG.128).
// ---------------------------------------------------------------------------
__global__ void __launch_bounds__(256) k_step(int step, int par,
        const float* __restrict__ pri,
        const float* __restrict__ encw, const float* __restrict__ encb,
        const float* __restrict__ Mw,   const float* __restrict__ Mb,
        const float* __restrict__ Uw,   const float* __restrict__ Ub,
        const float* __restrict__ dnw,  const float* __restrict__ dnb,
        const float* __restrict__ duw,  const float* __restrict__ dub,
        const float* __restrict__ termw,const float* __restrict__ termb,
        float* __restrict__ out, int N, int T, int KS8) {
    __shared__ float s_encw[34 * HID];
    __shared__ float s_Uw[64 * HID];
    __shared__ float s_Mw[64 * HID];
    __shared__ float s_dnw[64];
    __shared__ float s_duw[65];
    __shared__ float s_termw[HID];
    __shared__ __align__(16) float s_um[8][64];
    __shared__ __align__(8) float s_zs[HID][18];
    __shared__ __align__(8) float s_us[HID][18];
    __shared__ float s_red[8];

    int tid = threadIdx.x;
    bool lastStep = (step >= T - 2);

    // weight prefetch into smem — latency hidden behind the edge phase
    if (!lastStep) {
        for (int i = tid; i < 34 * HID; i += 256) s_encw[i] = encw[i];
        for (int i = tid; i < 64 * HID; i += 256) s_Mw[i] = Mw[i];
    }
    for (int i = tid; i < 64 * HID; i += 256) s_Uw[i] = Uw[i];
    if (tid < 64) s_dnw[tid] = dnw[tid];
    if (tid < 65) s_duw[tid] = duw[tid];
    if (tid < HID) s_termw[tid] = termw[tid];

    int w = tid >> 5, j = tid & 31, qb = w * 2;
    int n0 = blockIdx.x * 16 + qb;
    bool active = (n0 < N);
    float locmax = -INFINITY;

    // ---------------- edge phase: lane-group vector gathers -----------------
    float z0 = 0.f, z1 = 0.f;
    if (active) {
        int r = n0 * HID + j;
        z0 = g_z[r]; z1 = g_z[r + HID];       // prefetch, overlaps gathers
        const float* __restrict__ Aold = g_A[par];
        int g = j >> 3, c4 = (j & 7) << 2;    // group 0..3, col base 4*(j&7)
        const float4 fw4 = *(const float4*)(Mw + 64 * HID + c4);
        #pragma unroll
        for (int qi = 0; qi < 2; qi++) {
            const int2* __restrict__ pp = g_pair + (long)(n0 + qi) * KS8 + g;
            float mx = -INFINITY, my = -INFINITY, mz = -INFINITY, mw2 = -INFINITY;
            #pragma unroll 2
            for (int k = 0; k < KS8; k += 8) {
                int2 p0 = __ldg(pp + k);
                int2 p1 = __ldg(pp + k + 4);
                const float4 a0 = *(const float4*)(Aold + (p0.x << 5) + c4);
                const float4 a1 = *(const float4*)(Aold + (p1.x << 5) + c4);
                float f0 = __int_as_float(p0.y);
                float f1 = __int_as_float(p1.y);
                mx = fmaxf(mx, fmaf(f0, fw4.x, a0.x));
                my = fmaxf(my, fmaf(f0, fw4.y, a0.y));
                mz = fmaxf(mz, fmaf(f0, fw4.z, a0.z));
                mw2 = fmaxf(mw2, fmaf(f0, fw4.w, a0.w));
                mx = fmaxf(mx, fmaf(f1, fw4.x, a1.x));
                my = fmaxf(my, fmaf(f1, fw4.y, a1.y));
                mz = fmaxf(mz, fmaf(f1, fw4.z, a1.z));
                mw2 = fmaxf(mw2, fmaf(f1, fw4.w, a1.w));
            }
            // combine the 4 lane-groups (xor 8, xor 16)
            mx  = fmaxf(mx,  __shfl_xor_sync(0xffffffffu, mx, 8));
            my  = fmaxf(my,  __shfl_xor_sync(0xffffffffu, my, 8));
            mz  = fmaxf(mz,  __shfl_xor_sync(0xffffffffu, mz, 8));
            mw2 = fmaxf(mw2, __shfl_xor_sync(0xffffffffu, mw2, 8));
            mx  = fmaxf(mx,  __shfl_xor_sync(0xffffffffu, mx, 16));
            my  = fmaxf(my,  __shfl_xor_sync(0xffffffffu, my, 16));
            mz  = fmaxf(mz,  __shfl_xor_sync(0xffffffffu, mz, 16));
            mw2 = fmaxf(mw2, __shfl_xor_sync(0xffffffffu, mw2, 16));
            if (g == 0)
                *(float4*)&s_um[w][qi * 32 + c4] = make_float4(mx, my, mz, mw2);
        }
        __syncwarp();
    }
    __syncthreads();   // weights ready

    // ---------------- node phase (R5 layout) --------------------------------
    if (active) {
        int r = n0 * HID + j;
        float u0 = g_Bc[r]       + s_um[w][j];
        float u1 = g_Bc[r + HID] + s_um[w][32 + j];
        s_zs[j][qb + 0] = z0; s_zs[j][qb + 1] = z1;
        s_us[j][qb + 0] = u0; s_us[j][qb + 1] = u1;
        __syncwarp();
        float ub = __ldg(Ub + j);
        float nh0 = ub, nh1 = ub;
        #pragma unroll
        for (int i = 0; i < HID; i++) {
            float wz = s_Uw[i * HID + j], wu = s_Uw[(HID + i) * HID + j];
            float2 zq = *(const float2*)&s_zs[i][qb];
            float2 uq = *(const float2*)&s_us[i][qb];
            nh0 = fmaf(zq.x, wz, nh0); nh0 = fmaf(uq.x, wu, nh0);
            nh1 = fmaf(zq.y, wz, nh1); nh1 = fmaf(uq.y, wu, nh1);
        }
        float tw = s_termw[j], d1 = s_dnw[j], d2 = s_dnw[HID + j];
        float e1 = s_duw[j], e2 = s_duw[HID + j];
        float l0 = nh0 * tw, l1 = nh1 * tw;
        float qd0 = fmaf(nh0, d1, z0 * d2), qd1 = fmaf(nh1, d1, z1 * d2);
        float rd0 = fmaf(nh0, e1, z0 * e2), rd1 = fmaf(nh1, e1, z1 * e2);
        #pragma unroll
        for (int o = 16; o; o >>= 1) {
            l0  += __shfl_xor_sync(0xffffffffu, l0, o);
            l1  += __shfl_xor_sync(0xffffffffu, l1, o);
            qd0 += __shfl_xor_sync(0xffffffffu, qd0, o);
            qd1 += __shfl_xor_sync(0xffffffffu, qd1, o);
            rd0 += __shfl_xor_sync(0xffffffffu, rd0, o);
            rd1 += __shfl_xor_sync(0xffffffffu, rd1, o);
        }
        float tb = __ldg(termb);
        locmax = fmaxf(l0, l1) + tb;
        float db = __ldg(dnb), du0 = __ldg(dub), dw64 = s_duw[64];
        float nn0 = qd0 + db, nn1 = qd1 + db;
        float ns0 = fmaf(nn0, dw64, rd0 + du0);
        float ns1 = fmaf(nn1, dw64, rd1 + du0);
        if (j < 2) {
            float nsv = (j == 0) ? ns0 : ns1;
            float nnv = (j == 0) ? nn0 : nn1;
            out[(step + 1) * N + n0 + j] = nsv;                    // preds
            out[T * N + T + (n0 + j) * (T - 1) + step] = nnv;      // preds_nextnode
        }
        if (!lastStep) {
            s_zs[j][qb + 0] = nh0; s_zs[j][qb + 1] = nh1;
            __syncwarp();
            const float2 p2 = *(const float2*)(pri + n0);
            float eb = __ldg(encb + j);
            float w0 = s_encw[j], w33 = s_encw[33 * HID + j];
            float zn0 = fmaf(ns0, w0, fmaf(p2.x, w33, eb));
            float zn1 = fmaf(ns1, w0, fmaf(p2.y, w33, eb));
            #pragma unroll
            for (int i = 0; i < HID; i++) {
                float we = s_encw[(1 + i) * HID + j];
                float2 hq = *(const float2*)&s_zs[i][qb];
                zn0 = fmaf(hq.x, we, zn0); zn1 = fmaf(hq.y, we, zn1);
            }
            s_us[j][qb + 0] = zn0; s_us[j][qb + 1] = zn1;
            __syncwarp();
            float A0 = 0, A1 = 0, B0 = 0, B1 = 0;
            #pragma unroll
            for (int i = 0; i < HID; i++) {
                float wa = s_Mw[i * HID + j], wb = s_Mw[(HID + i) * HID + j];
                float2 zq = *(const float2*)&s_us[i][qb];
                A0 = fmaf(zq.x, wa, A0); B0 = fmaf(zq.x, wb, B0);
                A1 = fmaf(zq.y, wa, A1); B1 = fmaf(zq.y, wb, B1);
            }
            float mb = __ldg(Mb + j);
            float* __restrict__ Anew = g_A[par ^ 1];
            g_z[r] = zn0; g_z[r + HID] = zn1;
            Anew[r] = A0; Anew[r + HID] = A1;
            g_Bc[r] = B0 + mb; g_Bc[r + HID] = B1 + mb;
        }
    }

    if (j == 0) s_red[w] = active ? locmax : -INFINITY;
    __syncthreads();
    if (tid == 0) {
        float m = -INFINITY;
        #pragma unroll
        for (int ww = 0; ww < 8; ww++) m = fmaxf(m, s_red[ww]);
        g_blockmax[step * 1024 + blockIdx.x] = m;
    }
}

// ---------------------------------------------------------------------------
// Finalize: preds_stop[0]=0, preds_stop[t+1]=sigmoid(max_blocks blockmax[t])
// ---------------------------------------------------------------------------
__global__ void k_final(float* __restrict__ out, int N, int T, int nblocks) {
    __shared__ float s_red[256];
    int t = blockIdx.x;
    float m = -INFINITY;
    for (int b = threadIdx.x; b < nblocks; b += blockDim.x)
        m = fmaxf(m, g_blockmax[t * 1024 + b]);
    s_red[threadIdx.x] = m;
    __syncthreads();
    for (int s = 128; s; s >>= 1) {
        if (threadIdx.x < s)
            s_red[threadIdx.x] = fmaxf(s_red[threadIdx.x], s_red[threadIdx.x + s]);
        __syncthreads();
    }
    if (threadIdx.x == 0) {
        float v = s_red[0];
        out[T * N + 1 + t] = 1.0f / (1.0f + expf(-v));
        if (t == 0) out[T * N] = 0.0f;
    }
}

// ---------------------------------------------------------------------------
extern "C" void kernel_launch(void* const* d_in, const int* in_sizes, int n_in,
                              void* d_out, int out_size) {
    const float* states   = (const float*)d_in[0];
    const float* priority = (const float*)d_in[1];
    const float* edges    = (const float*)d_in[2];
    const int*   src      = (const int*)d_in[3];
    const float* enc_w    = (const float*)d_in[5];
    const float* enc_b    = (const float*)d_in[6];
    const float* M_w      = (const float*)d_in[7];
    const float* M_b      = (const float*)d_in[8];
    const float* U_w      = (const float*)d_in[9];
    const float* U_b      = (const float*)d_in[10];
    const float* dn_w     = (const float*)d_in[11];
    const float* dn_b     = (const float*)d_in[12];
    const float* du_w     = (const float*)d_in[13];
    const float* du_b     = (const float*)d_in[14];
    const float* term_w   = (const float*)d_in[15];
    const float* term_b   = (const float*)d_in[16];
    float* out = (float*)d_out;

    int N = in_sizes[1];
    int E = in_sizes[3];
    int T = in_sizes[0] / N;
    int Kc = E / N;
    int Erem = E - Kc * N;
    int KS = Kc + (Erem ? 1 : 0);
    int KS8 = (KS + 7) & ~7;          // pad to multiple of 8

    int ptotal = N * KS8;
    k_prep<<<(ptotal + 255) / 256, 256>>>(edges, src, N, E, Kc, KS8, Erem);

    int nb = (N + 15) / 16;
    k_init<<<nb, 256>>>(states, priority, enc_w, enc_b, M_w, M_b, out, N);

    for (int t = 0; t < T - 1; t++) {
        k_step<<<nb, 256>>>(t, t & 1, priority, enc_w, enc_b, M_w, M_b,
                            U_w, U_b, dn_w, dn_b, du_w, du_b,
                            term_w, term_b, out, N, T, KS8);
    }
    k_final<<<T - 1, 256>>>(out, N, T, nb);
}